// round 14
// baseline (speedup 1.0000x reference)
#include <cuda_runtime.h>
#include <cuda_fp16.h>
#include <cstdint>

#define NTH    256
#define ETILE  256
#define MAX_E  800000
#define NCAP   50048

// ---- edge kernel smem layout (bytes) ----
#define SM_A    0          // 256 rows x 144 B: 36864
#define SM_W1E  36864      // 256 rows x 144 B: 36864
#define SMEM_EDGE 73728

// ---- pcomp kernel smem layout ----
#define PC_B1   0          // float[256]
#define PC_A    1024       // 128 rows x 272 B: 34816
#define PC_W    35840      // 256 rows x 272 B: 69632
#define SMEM_PC 105472

// ---- out kernel smem layout ----
#define FB2     0          // float[128]
#define FA      1024       // 128 rows x 528 B: 67584
#define FW      68608      // 128 rows x 528 B: 67584
#define SMEM_OUT 136192

__device__ int g_cnt[2];
__device__ int g_list[2 * MAX_E];
__device__ int g_deg[2 * NCAP];
// packed fp16 weight images in smem (ldmatrix) layout, incl. row pads
__device__ uint32_t gW1eh[2 * 256 * 36];    // [f][n<256][kpair<32 +pad]
__device__ uint32_t gW1xh[2 * 256 * 68];    // [f][n<256][kpair<64 +pad]
__device__ uint32_t gW2h [2 * 128 * 132];   // [f][n<128][kpair<128 +pad]
// P in fp16, coalesced: [f][node][j2<16][q<4] uint2; off = node*512+j2*32+q*8
__device__ uint2 g_Ph[2 * (size_t)NCAP * 64];
// per-node hidden aggregate: H[f][node][256] fp32
__device__ float g_H[2 * (size_t)NCAP * 256];

// ---------------- helpers ----------------
static __device__ __forceinline__ uint32_t smem_u32(const void* p) {
    uint32_t a;
    asm("{ .reg .u64 t; cvta.to.shared.u64 t, %1; cvt.u32.u64 %0, t; }"
        : "=r"(a) : "l"(p));
    return a;
}
static __device__ __forceinline__ uint32_t pack_h2(float lo, float hi) {
    uint32_t r;
    asm("cvt.rn.f16x2.f32 %0, %1, %2;" : "=r"(r) : "f"(hi), "f"(lo));
    return r;
}
static __device__ __forceinline__ float2 unpack_h2(uint32_t u) {
    __half2 h = *reinterpret_cast<__half2*>(&u);
    return __half22float2(h);
}
static __device__ __forceinline__ void sts128(uint32_t a, uint32_t r0, uint32_t r1,
                                              uint32_t r2, uint32_t r3) {
    asm volatile("st.shared.v4.b32 [%0], {%1,%2,%3,%4};"
                 :: "r"(a), "r"(r0), "r"(r1), "r"(r2), "r"(r3) : "memory");
}
static __device__ __forceinline__ void ldsm_x4(uint32_t r[4], uint32_t addr) {
    asm volatile("ldmatrix.sync.aligned.m8n8.x4.shared.b16 {%0,%1,%2,%3}, [%4];"
                 : "=r"(r[0]), "=r"(r[1]), "=r"(r[2]), "=r"(r[3]) : "r"(addr));
}
static __device__ __forceinline__ void mma_f16(float d[4], const uint32_t a[4],
                                               const uint32_t b[2]) {
    asm("mma.sync.aligned.m16n8k16.row.col.f32.f16.f16.f32 "
        "{%0,%1,%2,%3}, {%4,%5,%6,%7}, {%8,%9}, {%0,%1,%2,%3};"
        : "+f"(d[0]), "+f"(d[1]), "+f"(d[2]), "+f"(d[3])
        : "r"(a[0]), "r"(a[1]), "r"(a[2]), "r"(a[3]), "r"(b[0]), "r"(b[1]));
}
static __device__ __forceinline__ void red_add2(float* p, float a, float b) {
    asm volatile("red.global.add.v2.f32 [%0], {%1,%2};"
                 :: "l"(p), "f"(a), "f"(b) : "memory");
}
static __device__ __forceinline__ void cpa16(uint32_t d, const void* s) {
    asm volatile("cp.async.ca.shared.global [%0], [%1], 16;"
                 :: "r"(d), "l"(s) : "memory");
}
#define CP_COMMIT() asm volatile("cp.async.commit_group;" ::: "memory")
#define CP_WAIT(n)  asm volatile("cp.async.wait_group %0;" :: "n"(n) : "memory")

// ---------------- setup kernels ----------------
__global__ void prep_kernel(const float* __restrict__ W1o, const float* __restrict__ W1i,
                            const float* __restrict__ W2o, const float* __restrict__ W2i) {
    int idx = blockIdx.x * 256 + threadIdx.x;
    if (idx < 2) g_cnt[idx] = 0;
    if (idx < 16384) {                          // W1e: [f][nl<256][p<32]
        int p = idx & 31; int t = idx >> 5;
        int nl = t & 255; int f = t >> 8;
        const float* W = f ? W1i : W1o;
        gW1eh[(f * 256 + nl) * 36 + p] =
            pack_h2(W[(128 + 2 * p) * 256 + nl], W[(129 + 2 * p) * 256 + nl]);
    } else if (idx < 49152) {                   // W1x: [f][nl<256][p<64]
        int i = idx - 16384;
        int p = i & 63; int t = i >> 6;
        int nl = t & 255; int f = t >> 8;
        const float* W = f ? W1i : W1o;
        gW1xh[(f * 256 + nl) * 68 + p] =
            pack_h2(W[(2 * p) * 256 + nl], W[(2 * p + 1) * 256 + nl]);
    } else if (idx < 81920) {                   // W2: [f][nl<128][p<128]
        int i = idx - 49152;
        int p = i & 127; int t = i >> 7;
        int nl = t & 127; int f = t >> 7;
        const float* W = f ? W2i : W2o;
        gW2h[(f * 128 + nl) * 132 + p] =
            pack_h2(W[(2 * p) * 128 + nl], W[(2 * p + 1) * 128 + nl]);
    }
}

__global__ void partition_kernel(const int* __restrict__ ei, int E) {
    __shared__ int s_cnt[2], s_base[2];
    int tid = threadIdx.x;
    if (tid < 2) s_cnt[tid] = 0;
    __syncthreads();
    int e = blockIdx.x * blockDim.x + tid;
    bool valid = e < E;
    int r = 0, c = 0;
    if (valid) { r = ei[e]; c = ei[E + e]; }
    int lane = tid & 31;
    bool po = valid && (r < c);
    bool pi = valid && (r > c);
    if (po) atomicAdd(&g_deg[r], 1);
    if (pi) atomicAdd(&g_deg[NCAP + r], 1);
    unsigned mo = __ballot_sync(0xffffffffu, po);
    unsigned mi = __ballot_sync(0xffffffffu, pi);
    int lo = __ffs(mo) - 1, li = __ffs(mi) - 1;
    int wo = 0, wi = 0;
    if (mo && lane == lo) wo = atomicAdd(&s_cnt[0], __popc(mo));
    if (mi && lane == li) wi = atomicAdd(&s_cnt[1], __popc(mi));
    __syncthreads();
    if (tid == 0) s_base[0] = atomicAdd(&g_cnt[0], s_cnt[0]);
    if (tid == 1) s_base[1] = atomicAdd(&g_cnt[1], s_cnt[1]);
    __syncthreads();
    if (mo) wo = __shfl_sync(0xffffffffu, wo, lo);
    if (mi) wi = __shfl_sync(0xffffffffu, wi, li);
    unsigned lt = (1u << lane) - 1u;
    if (po) g_list[s_base[0] + wo + __popc(mo & lt)] = e;
    if (pi) g_list[MAX_E + s_base[1] + wi + __popc(mi & lt)] = e;
}

// ---------------- P precompute: P = x @ W1x + b1 (fp16, [node][j2][q]) -----
__global__ __launch_bounds__(256, 1)
void pcomp_kernel(const float* __restrict__ x,
                  const float* __restrict__ b1o, const float* __restrict__ b1i,
                  int N) {
    int f = blockIdx.y;
    int base = blockIdx.x * 128;
    if (base >= N) return;
    const float* b1 = f ? b1i : b1o;

    extern __shared__ __align__(16) char smem[];
    uint32_t sb = smem_u32(smem);
    uint32_t sbA = sb + PC_A, sbW = sb + PC_W;
    int tid = threadIdx.x, wid = tid >> 5, lane = tid & 31;

    {
        const uint32_t* src = gW1xh + (size_t)f * 256 * 68;
        #pragma unroll
        for (int i = 0; i < 17; i++) {
            int s = tid + i * 256;
            cpa16(sbW + s * 16, src + s * 4);
        }
        CP_COMMIT();
    }
    ((float*)(smem + PC_B1))[tid] = b1[tid];

    {
        int r = tid & 127, h = tid >> 7;
        int node = min(base + r, N - 1);
        const float4* xr = (const float4*)(x + (size_t)node * 128);
        #pragma unroll
        for (int q = 0; q < 8; q++) {
            float4 a = xr[h * 16 + 2 * q], b = xr[h * 16 + 2 * q + 1];
            sts128(sbA + r * 272 + h * 128 + q * 16,
                   pack_h2(a.x, a.y), pack_h2(a.z, a.w),
                   pack_h2(b.x, b.y), pack_h2(b.z, b.w));
        }
    }
    CP_WAIT(0);
    __syncthreads();

    uint32_t aB = sbA + (wid * 16 + (lane & 15)) * 272 + (lane >> 4) * 16;
    uint32_t bB = sbW + (uint32_t)((lane & 7) + ((lane >> 4) << 3)) * 272
                + (uint32_t)(((lane >> 3) & 1) << 4);

    float acc[32][4];
    #pragma unroll
    for (int j = 0; j < 32; j++)
        #pragma unroll
        for (int p = 0; p < 4; p++) acc[j][p] = 0.0f;

    for (int s = 0; s < 8; s++) {
        uint32_t af[4]; ldsm_x4(af, aB + s * 32);
        #pragma unroll
        for (int nt2 = 0; nt2 < 16; nt2++) {
            uint32_t bf4[4];
            ldsm_x4(bf4, bB + nt2 * 4352 + s * 32);
            mma_f16(acc[2 * nt2],     af, bf4);
            mma_f16(acc[2 * nt2 + 1], af, bf4 + 2);
        }
    }

    // epilogue: + b1, pack fp16, write [node][j2][q] uint2
    {
        const float* b1s = (const float*)(smem + PC_B1);
        int q = lane & 3, t2 = 2 * q;
        int m1 = wid * 16 + (lane >> 2), m2 = m1 + 8;
        int n1 = base + m1, n2 = base + m2;
        uint2* p1 = g_Ph + ((size_t)f * NCAP + n1) * 64 + q;
        uint2* p2 = g_Ph + ((size_t)f * NCAP + n2) * 64 + q;
        #pragma unroll
        for (int j2 = 0; j2 < 16; j2++) {
            int j = 2 * j2;
            float b0 = b1s[8 * j + t2],        b1v = b1s[8 * j + t2 + 1];
            float b2v = b1s[8 * (j + 1) + t2], b3 = b1s[8 * (j + 1) + t2 + 1];
            if (n1 < N) {
                uint2 v;
                v.x = pack_h2(acc[j][0] + b0,      acc[j][1] + b1v);
                v.y = pack_h2(acc[j + 1][0] + b2v, acc[j + 1][1] + b3);
                p1[j2 * 4] = v;
            }
            if (n2 < N) {
                uint2 v;
                v.x = pack_h2(acc[j][2] + b0,      acc[j][3] + b1v);
                v.y = pack_h2(acc[j + 1][2] + b2v, acc[j + 1][3] + b3);
                p2[j2 * 4] = v;
            }
        }
    }
}

// ---------------- edge kernel: H[row] += relu(ea@W1e + P[col]) -------------
__global__ __launch_bounds__(NTH, 2)
void edge_kernel(const int* __restrict__ ei, const float* __restrict__ ea, int E) {
    int f = blockIdx.y;
    int cnt = g_cnt[f];
    int base = blockIdx.x * ETILE;
    if (base >= cnt) return;
    int nvalid = min(ETILE, cnt - base);
    const int* list = g_list + f * MAX_E;

    extern __shared__ __align__(16) char smem[];
    uint32_t sb = smem_u32(smem);
    int tid = threadIdx.x, wid = tid >> 5, lane = tid & 31;
    int q = lane & 3, t2 = 2 * q;
    int m1 = wid * 32 + (lane >> 2);

    const char* Pb = (const char*)g_Ph + (size_t)f * NCAP * 512;
    float* Hf = g_H + (size_t)f * NCAP * 256;

    uint32_t poff[4];
    int rowv[4];
    bool okt[4];
    #pragma unroll
    for (int t = 0; t < 4; t++) {
        int m = m1 + t * 8;
        okt[t] = m < nvalid;
        int e = __ldg(list + base + min(m, nvalid - 1));
        rowv[t] = __ldg(ei + e);
        int node = __ldg(ei + E + e);
        poff[t] = (uint32_t)node * 512u + (uint32_t)q * 8u;
    }

    // stream W1e: 2304 x 16B
    {
        const uint32_t* src = gW1eh + (size_t)f * 256 * 36;
        #pragma unroll
        for (int i = 0; i < 9; i++) {
            int s = tid + i * NTH;
            cpa16(sb + SM_W1E + s * 16, src + s * 4);
        }
        CP_COMMIT();
    }

    // gather own edge's ea row -> fp16 smem A (row = tid)
    {
        int e = __ldg(list + base + min(tid, nvalid - 1));
        const float4* er = (const float4*)(ea + (size_t)e * 64);
        #pragma unroll
        for (int qq = 0; qq < 8; qq++) {
            float4 a = er[2 * qq], b = er[2 * qq + 1];
            sts128(sb + SM_A + tid * 144 + qq * 16,
                   pack_h2(a.x, a.y), pack_h2(a.z, a.w),
                   pack_h2(b.x, b.y), pack_h2(b.z, b.w));
        }
    }
    CP_WAIT(0);
    __syncthreads();

    uint32_t bo144 = (uint32_t)((lane & 7) + ((lane >> 4) << 3)) * 144
                   + (uint32_t)(((lane >> 3) & 1) << 4);

    // A-fragments: two m16 tiles (m-window wid*32), 4 k16-steps
    uint32_t af1[2][4][4];
    #pragma unroll
    for (int t = 0; t < 2; t++) {
        uint32_t aB = sb + SM_A + (wid * 32 + t * 16 + (lane & 15)) * 144
                    + (lane >> 4) * 16;
        #pragma unroll
        for (int s = 0; s < 4; s++) ldsm_x4(af1[t][s], aB + s * 32);
    }

    uint32_t bW1 = sb + SM_W1E + bo144;

    #pragma unroll 4
    for (int j2 = 0; j2 < 16; j2++) {
        uint2 u[4];
        #pragma unroll
        for (int t = 0; t < 4; t++)
            u[t] = *(const uint2*)(Pb + poff[t] + j2 * 32);
        // GEMM1 into zero acc
        float a1[2][2][4] = {};
        #pragma unroll
        for (int s = 0; s < 4; s++) {
            uint32_t bf4[4];
            ldsm_x4(bf4, bW1 + j2 * 2304 + s * 32);
            #pragma unroll
            for (int t = 0; t < 2; t++) {
                mma_f16(a1[t][0], af1[t][s], bf4);
                mma_f16(a1[t][1], af1[t][s], bf4 + 2);
            }
        }
        // +P, relu, scatter-add into H
        #pragma unroll
        for (int t = 0; t < 2; t++) {
            #pragma unroll
            for (int half = 0; half < 2; half++) {
                int col = 16 * j2 + 8 * half + t2;
                float2 p0 = unpack_h2(half ? u[2 * t].y : u[2 * t].x);
                if (okt[2 * t])
                    red_add2(Hf + (size_t)rowv[2 * t] * 256 + col,
                             fmaxf(a1[t][half][0] + p0.x, 0.f),
                             fmaxf(a1[t][half][1] + p0.y, 0.f));
                float2 p1 = unpack_h2(half ? u[2 * t + 1].y : u[2 * t + 1].x);
                if (okt[2 * t + 1])
                    red_add2(Hf + (size_t)rowv[2 * t + 1] * 256 + col,
                             fmaxf(a1[t][half][2] + p1.x, 0.f),
                             fmaxf(a1[t][half][3] + p1.y, 0.f));
            }
        }
    }
}

// ---------------- out kernel: out = H_fp16 @ W2 + deg*b2 -------------------
__global__ __launch_bounds__(256, 1)
void out_kernel(const float* __restrict__ b2o, const float* __restrict__ b2i,
                int N, float* __restrict__ out) {
    int f = blockIdx.y;
    int base = blockIdx.x * 128;
    if (base >= N) return;
    int colOff = f ? 0 : 128;
    const float* b2 = f ? b2i : b2o;

    extern __shared__ __align__(16) char smem[];
    uint32_t sb = smem_u32(smem);
    int tid = threadIdx.x, wid = tid >> 5, lane = tid & 31;

    {
        const uint32_t* src = gW2h + (size_t)f * 128 * 132;
        #pragma unroll
        for (int i = 0; i < 17; i++) {
            int s = tid + i * 256;
            if (s < 4224) cpa16(sb + FW + s * 16, src + s * 4);
        }
        CP_COMMIT();
    }
    if (tid < 128) ((float*)(smem + FB2))[tid] = b2[tid];

    // load H rows -> fp16 smem A, stride 528 B
    {
        int r = tid & 127, h = tid >> 7;
        int node = min(base + r, N - 1);
        const float4* Hr = (const float4*)(g_H + ((size_t)f * NCAP + node) * 256
                                           + h * 128);
        #pragma unroll
        for (int i = 0; i < 16; i++) {
            float4 a = Hr[2 * i], b = Hr[2 * i + 1];
            sts128(sb + FA + r * 528 + h * 256 + i * 16,
                   pack_h2(a.x, a.y), pack_h2(a.z, a.w),
                   pack_h2(b.x, b.y), pack_h2(b.z, b.w));
        }
    }
    CP_WAIT(0);
    __syncthreads();

    uint32_t aB = sb + FA + (wid * 16 + (lane & 15)) * 528 + (lane >> 4) * 16;
    uint32_t bB = sb + FW + (uint32_t)((lane & 7) + ((lane >> 4) << 3)) * 528
                + (uint32_t)(((lane >> 3) & 1) << 4);

    float acc[16][4];
    #pragma unroll
    for (int j = 0; j < 16; j++)
        #pragma unroll
        for (int p = 0; p < 4; p++) acc[j][p] = 0.0f;

    for (int s = 0; s < 16; s++) {
        uint32_t af[4]; ldsm_x4(af, aB + s * 32);
        #pragma unroll
        for (int nt2 = 0; nt2 < 8; nt2++) {
            uint32_t bf4[4];
            ldsm_x4(bf4, bB + nt2 * 8448 + s * 32);
            mma_f16(acc[2 * nt2],     af, bf4);
            mma_f16(acc[2 * nt2 + 1], af, bf4 + 2);
        }
    }

    // epilogue: + deg*b2, dense writes
    {
        const float* b2s = (const float*)(smem + FB2);
        int q = lane & 3, t2 = 2 * q;
        int m1 = wid * 16 + (lane >> 2), m2 = m1 + 8;
        int n1 = base + m1, n2 = base + m2;
        if (n1 < N) {
            float d = (float)g_deg[f * NCAP + n1];
            float* o = out + (size_t)n1 * 256 + colOff;
            #pragma unroll
            for (int nt = 0; nt < 16; nt++) {
                int n0 = 8 * nt + t2;
                *(float2*)(o + n0) = make_float2(acc[nt][0] + d * b2s[n0],
                                                 acc[nt][1] + d * b2s[n0 + 1]);
            }
        }
        if (n2 < N) {
            float d = (float)g_deg[f * NCAP + n2];
            float* o = out + (size_t)n2 * 256 + colOff;
            #pragma unroll
            for (int nt = 0; nt < 16; nt++) {
                int n0 = 8 * nt + t2;
                *(float2*)(o + n0) = make_float2(acc[nt][2] + d * b2s[n0],
                                                 acc[nt][3] + d * b2s[n0 + 1]);
            }
        }
    }
}

// ---------------- host launch ----------------
extern "C" void kernel_launch(void* const* d_in, const int* in_sizes, int n_in,
                              void* d_out, int out_size) {
    const float* x   = (const float*)d_in[0];
    const int*   ei  = (const int*)  d_in[1];
    const float* ea  = (const float*)d_in[2];
    const float* W1o = (const float*)d_in[3];
    const float* b1o = (const float*)d_in[4];
    const float* W2o = (const float*)d_in[5];
    const float* b2o = (const float*)d_in[6];
    const float* W1i = (const float*)d_in[7];
    const float* b1i = (const float*)d_in[8];
    const float* W2i = (const float*)d_in[9];
    const float* b2i = (const float*)d_in[10];
    float* out = (float*)d_out;
    int E = in_sizes[1] / 2;
    int N = in_sizes[0] / 128;
    if (N > NCAP) N = NCAP;

    static float* dH = nullptr;
    static int* dDeg = nullptr;
    static bool attr_set = false;
    if (!attr_set) {
        cudaFuncSetAttribute(edge_kernel, cudaFuncAttributeMaxDynamicSharedMemorySize,
                             SMEM_EDGE);
        cudaFuncSetAttribute(pcomp_kernel, cudaFuncAttributeMaxDynamicSharedMemorySize,
                             SMEM_PC);
        cudaFuncSetAttribute(out_kernel, cudaFuncAttributeMaxDynamicSharedMemorySize,
                             SMEM_OUT);
        cudaGetSymbolAddress((void**)&dH, g_H);
        cudaGetSymbolAddress((void**)&dDeg, g_deg);
        attr_set = true;
    }

    cudaMemsetAsync(dH, 0, 2 * (size_t)NCAP * 256 * sizeof(float));
    cudaMemsetAsync(dDeg, 0, 2 * NCAP * sizeof(int));
    prep_kernel<<<320, 256>>>(W1o, W1i, W2o, W2i);   // also resets g_cnt
    partition_kernel<<<(E + 511) / 512, 512>>>(ei, E);
    pcomp_kernel<<<dim3((N + 127) / 128, 2), 256, SMEM_PC>>>(x, b1o, b1i, N);

    dim3 egrid((E + ETILE - 1) / ETILE, 2);
    edge_kernel<<<egrid, NTH, SMEM_EDGE>>>(ei, ea, E);

    dim3 ogrid((N + 127) / 128, 2);
    out_kernel<<<ogrid, 256, SMEM_OUT>>>(b2o, b2i, N, out);
}